// round 2
// baseline (speedup 1.0000x reference)
#include <cuda_runtime.h>
#include <math.h>

#define NN 50000
#define DD 128
#define HH 4
#define CC 32
#define LL 3
#define EE 800000
#define SLOPE 0.2f
#define BN_EPS 1e-5

// ---------------- scratch (static device globals; no allocation) ----------------
__device__ float g_xl[NN * DD];
__device__ float g_xr[NN * DD];
__device__ float g_xres[NN * DD];
__device__ float g_h[NN * DD];
__device__ float g_x[NN * DD];
__device__ int   g_rowptr[NN + 1];
__device__ int   g_cursor[NN];
__device__ int   g_cnt[NN];
__device__ int   g_col[EE];
__device__ double g_sum[DD];
__device__ double g_sumsq[DD];
__device__ int   g_is64;   // edge_index dtype flag: 1 = int64, 0 = int32

// ---------------- edge_index dtype detection ----------------
// If the buffer holds int64 values < 2^31, every odd 32-bit word is zero.
__global__ void detect_dtype_k(const unsigned int* __restrict__ w) {
    if (threadIdx.x == 0 && blockIdx.x == 0) {
        int is64 = 1;
        for (int i = 1; i < 64; i += 2)
            if (w[i] != 0u) { is64 = 0; break; }
        g_is64 = is64;
    }
}

__device__ __forceinline__ int edge_val(const void* ei, long long idx) {
    if (g_is64) return (int)((const long long*)ei)[idx];
    return ((const int*)ei)[idx];
}

// ---------------- CSR build ----------------
__global__ void zero_cnt_k() {
    int i = blockIdx.x * blockDim.x + threadIdx.x;
    if (i < NN) g_cnt[i] = 0;
}

__global__ void count_k(const void* __restrict__ ei, int E) {
    int e = blockIdx.x * blockDim.x + threadIdx.x;
    if (e < E) {
        int dst = edge_val(ei, (long long)E + e);
        atomicAdd(&g_cnt[dst], 1);
    }
}

// single block, 1024 threads, chunked exclusive scan of g_cnt -> g_rowptr (+cursor copy)
__global__ void scan_k() {
    const int CH = (NN + 1023) / 1024;   // 49
    __shared__ int ssum[1024];
    int t = threadIdx.x;
    int base = t * CH;
    int local = 0;
    for (int i = 0; i < CH; i++) {
        int idx = base + i;
        if (idx < NN) local += g_cnt[idx];
    }
    ssum[t] = local;
    __syncthreads();
    for (int off = 1; off < 1024; off <<= 1) {
        int v = 0;
        if (t >= off) v = ssum[t - off];
        __syncthreads();
        ssum[t] += v;
        __syncthreads();
    }
    int run = (t == 0) ? 0 : ssum[t - 1];
    for (int i = 0; i < CH; i++) {
        int idx = base + i;
        if (idx < NN) {
            g_rowptr[idx] = run;
            g_cursor[idx] = run;
            run += g_cnt[idx];
        }
    }
    if (t == 0) g_rowptr[NN] = ssum[1023];
}

__global__ void fill_k(const void* __restrict__ ei, int E) {
    int e = blockIdx.x * blockDim.x + threadIdx.x;
    if (e < E) {
        int dst = edge_val(ei, (long long)E + e);
        int src = edge_val(ei, e);
        int pos = atomicAdd(&g_cursor[dst], 1);
        g_col[pos] = src;
    }
}

// ---------------- SGEMM: C[M,128] = A[M,128] @ B[128,128] (+ optional bias) ----------------
// BM=BN=64, BK=16, TM=TN=4, 256 threads.
__global__ void sgemm128(const float* __restrict__ A, const float* __restrict__ B,
                         const float* __restrict__ bias, float* __restrict__ C, int M)
{
    __shared__ float As[16][64];
    __shared__ float Bs[16][64];

    int tid = threadIdx.x;
    int col0 = blockIdx.x * 64;
    int row0 = blockIdx.y * 64;

    int tx = tid & 15;        // N direction, 16 * 4 = 64
    int ty = tid >> 4;        // M direction, 16 * 4 = 64

    float acc[4][4];
#pragma unroll
    for (int i = 0; i < 4; i++)
#pragma unroll
        for (int j = 0; j < 4; j++) acc[i][j] = 0.f;

    int lar = tid >> 2;       // A tile row 0..63
    int lak = tid & 3;        // A tile k-quad 0..3
    int lbk = tid >> 4;       // B tile k-row 0..15
    int lbc = tid & 15;       // B tile col-quad 0..15

    for (int k0 = 0; k0 < 128; k0 += 16) {
        // load A tile (guarded), store transposed
        float4 av;
        int gr = row0 + lar;
        if (gr < M)
            av = *(const float4*)&A[(size_t)gr * 128 + k0 + lak * 4];
        else
            av = make_float4(0.f, 0.f, 0.f, 0.f);
        As[lak * 4 + 0][lar] = av.x;
        As[lak * 4 + 1][lar] = av.y;
        As[lak * 4 + 2][lar] = av.z;
        As[lak * 4 + 3][lar] = av.w;

        // load B tile
        float4 bv = *(const float4*)&B[(size_t)(k0 + lbk) * 128 + col0 + lbc * 4];
        *(float4*)&Bs[lbk][lbc * 4] = bv;

        __syncthreads();

#pragma unroll
        for (int kk = 0; kk < 16; kk++) {
            float4 a = *(const float4*)&As[kk][ty * 4];
            float4 b = *(const float4*)&Bs[kk][tx * 4];
            float ar[4] = {a.x, a.y, a.z, a.w};
            float br[4] = {b.x, b.y, b.z, b.w};
#pragma unroll
            for (int i = 0; i < 4; i++)
#pragma unroll
                for (int j = 0; j < 4; j++)
                    acc[i][j] = fmaf(ar[i], br[j], acc[i][j]);
        }
        __syncthreads();
    }

    float bb[4] = {0.f, 0.f, 0.f, 0.f};
    if (bias) {
#pragma unroll
        for (int j = 0; j < 4; j++) bb[j] = bias[col0 + tx * 4 + j];
    }
#pragma unroll
    for (int i = 0; i < 4; i++) {
        int gr = row0 + ty * 4 + i;
        if (gr < M) {
            float4 o;
            o.x = acc[i][0] + bb[0];
            o.y = acc[i][1] + bb[1];
            o.z = acc[i][2] + bb[2];
            o.w = acc[i][3] + bb[3];
            *(float4*)&C[(size_t)gr * 128 + col0 + tx * 4] = o;
        }
    }
}

// ---------------- fused GATv2 per-node kernel ----------------
// One block (128 threads = 4 warps = 4 heads) per destination node.
// Single-pass softmax (no max subtraction; |e| is small for this model):
//   out = sum_e exp(e)*msg_e / sum_e exp(e)
__global__ void gat_node_k(const float* __restrict__ xl, const float* __restrict__ xr,
                           const float* __restrict__ xres, const float* __restrict__ bias,
                           const float* __restrict__ att, float* __restrict__ out)
{
    int v = blockIdx.x;
    int t = threadIdx.x;

    float xrv = xr[(size_t)v * DD + t];
    float a   = att[t];                // att[h*32 + c], t = h*32 + c

    float denom = 0.f, acc = 0.f;

    // self loop
    {
        float m = xl[(size_t)v * DD + t];
        float p = m + xrv;
        p = (p > 0.f) ? p : SLOPE * p;
        float sc = p * a;
#pragma unroll
        for (int o = 16; o > 0; o >>= 1)
            sc += __shfl_xor_sync(0xffffffffu, sc, o);
        float w = __expf(sc);
        denom += w;
        acc += w * m;
    }

    int j = g_rowptr[v];
    int e2 = g_rowptr[v + 1];
    for (; j + 2 <= e2; j += 2) {
        int s0 = g_col[j];
        int s1 = g_col[j + 1];
        float m0 = xl[(size_t)s0 * DD + t];
        float m1 = xl[(size_t)s1 * DD + t];
        float p0 = m0 + xrv; p0 = (p0 > 0.f) ? p0 : SLOPE * p0;
        float p1 = m1 + xrv; p1 = (p1 > 0.f) ? p1 : SLOPE * p1;
        float sc0 = p0 * a;
        float sc1 = p1 * a;
#pragma unroll
        for (int o = 16; o > 0; o >>= 1) {
            sc0 += __shfl_xor_sync(0xffffffffu, sc0, o);
            sc1 += __shfl_xor_sync(0xffffffffu, sc1, o);
        }
        float w0 = __expf(sc0);
        float w1 = __expf(sc1);
        denom += w0 + w1;
        acc = fmaf(w0, m0, acc);
        acc = fmaf(w1, m1, acc);
    }
    if (j < e2) {
        int s0 = g_col[j];
        float m0 = xl[(size_t)s0 * DD + t];
        float p0 = m0 + xrv; p0 = (p0 > 0.f) ? p0 : SLOPE * p0;
        float sc0 = p0 * a;
#pragma unroll
        for (int o = 16; o > 0; o >>= 1)
            sc0 += __shfl_xor_sync(0xffffffffu, sc0, o);
        float w0 = __expf(sc0);
        denom += w0;
        acc = fmaf(w0, m0, acc);
    }

    out[(size_t)v * DD + t] = acc / denom + bias[t] + xres[(size_t)v * DD + t];
}

// ---------------- BatchNorm ----------------
__global__ void bn_zero_k() {
    int t = threadIdx.x;
    if (t < DD) { g_sum[t] = 0.0; g_sumsq[t] = 0.0; }
}

__global__ void bn_stats_k(const float* __restrict__ x) {
    int t = threadIdx.x;                    // column, 128 threads
    int rows = (NN + gridDim.x - 1) / gridDim.x;
    int r0 = blockIdx.x * rows;
    int r1 = min(NN, r0 + rows);
    double s = 0.0, ss = 0.0;
    for (int r = r0; r < r1; r++) {
        float v = x[(size_t)r * DD + t];
        s += (double)v;
        ss += (double)v * (double)v;
    }
    atomicAdd(&g_sum[t], s);
    atomicAdd(&g_sumsq[t], ss);
}

__global__ void bn_apply_k(const float* __restrict__ x, const float* __restrict__ gamma,
                           const float* __restrict__ beta, float* __restrict__ y)
{
    int t = threadIdx.x;
    double mu = g_sum[t] / (double)NN;
    double var = g_sumsq[t] / (double)NN - mu * mu;
    float sc = (float)(1.0 / sqrt(var + BN_EPS)) * gamma[t];
    float sh = beta[t] - (float)mu * sc;
    int rows = (NN + gridDim.x - 1) / gridDim.x;
    int r0 = blockIdx.x * rows;
    int r1 = min(NN, r0 + rows);
    for (int r = r0; r < r1; r++) {
        float v = x[(size_t)r * DD + t] * sc + sh;
        v = (v > 0.f) ? v : SLOPE * v;
        y[(size_t)r * DD + t] = v;
    }
}

// ---------------- launch ----------------
extern "C" void kernel_launch(void* const* d_in, const int* in_sizes, int n_in,
                              void* d_out, int out_size)
{
    const float* x     = (const float*)d_in[0];
    const void*  ei    = (const void*)d_in[1];
    const float* Wl    = (const float*)d_in[2];
    const float* Wr    = (const float*)d_in[3];
    const float* att   = (const float*)d_in[4];
    const float* bias  = (const float*)d_in[5];
    const float* Wres  = (const float*)d_in[6];
    const float* gamma = (const float*)d_in[7];
    const float* beta  = (const float*)d_in[8];
    const float* Wout  = (const float*)d_in[9];
    const float* bout  = (const float*)d_in[10];
    float* out = (float*)d_out;

    int E = in_sizes[1] / 2;

    float *xl, *xr, *xres, *h, *xc;
    cudaGetSymbolAddress((void**)&xl,   g_xl);
    cudaGetSymbolAddress((void**)&xr,   g_xr);
    cudaGetSymbolAddress((void**)&xres, g_xres);
    cudaGetSymbolAddress((void**)&h,    g_h);
    cudaGetSymbolAddress((void**)&xc,   g_x);

    // dtype sniff + CSR build (reused for all 3 layers)
    detect_dtype_k<<<1, 32>>>((const unsigned int*)ei);
    zero_cnt_k<<<(NN + 255) / 256, 256>>>();
    count_k<<<(E + 255) / 256, 256>>>(ei, E);
    scan_k<<<1, 1024>>>();
    fill_k<<<(E + 255) / 256, 256>>>(ei, E);

    dim3 ggrid(128 / 64, (NN + 63) / 64);   // (2, 782)

    const float* xin = x;
    for (int i = 0; i < LL; i++) {
        sgemm128<<<ggrid, 256>>>(xin, Wl + (size_t)i * DD * DD, nullptr, xl, NN);
        sgemm128<<<ggrid, 256>>>(xin, Wr + (size_t)i * DD * DD, nullptr, xr, NN);
        sgemm128<<<ggrid, 256>>>(xin, Wres + (size_t)i * DD * DD, nullptr, xres, NN);
        gat_node_k<<<NN, 128>>>(xl, xr, xres, bias + (size_t)i * DD,
                                att + (size_t)i * HH * CC, h);
        bn_zero_k<<<1, DD>>>();
        bn_stats_k<<<512, DD>>>(h);
        bn_apply_k<<<512, DD>>>(h, gamma + (size_t)i * DD, beta + (size_t)i * DD, xc);
        xin = xc;
    }

    sgemm128<<<ggrid, 256>>>(xc, Wout, bout, out, NN);
}

// round 3
// speedup vs baseline: 1.3343x; 1.3343x over previous
#include <cuda_runtime.h>
#include <cuda_bf16.h>
#include <mma.h>
#include <math.h>

using namespace nvcuda;

#define NN 50000
#define NP 50048            // padded rows: 391 * 128
#define DD 128
#define HH 4
#define CC 32
#define LL 3
#define EE 800000
#define SLOPE 0.2f
#define BN_EPS 1e-5

// ---------------- scratch (static device globals; no allocation) ----------------
__device__ float g_xl[NP * DD];
__device__ float g_xr[NP * DD];
__device__ float g_xres[NP * DD];
__device__ float g_h[NP * DD];
__device__ int   g_rowptr[NN + 1];
__device__ int   g_cursor[NN];
__device__ int   g_cnt[NN];
__device__ int   g_col[EE];
__device__ int   g_bsum[128];
__device__ int   g_boff[128];
__device__ double g_sum[DD];
__device__ double g_sumsq[DD];
__device__ float g_bnsc[DD];
__device__ float g_bnsh[DD];
__device__ int   g_is64;

// ---------------- edge_index dtype detection ----------------
__global__ void detect_dtype_k(const unsigned int* __restrict__ w) {
    if (threadIdx.x == 0 && blockIdx.x == 0) {
        int is64 = 1;
        for (int i = 1; i < 64; i += 2)
            if (w[i] != 0u) { is64 = 0; break; }
        g_is64 = is64;
    }
}

__device__ __forceinline__ int edge_val(const void* ei, long long idx) {
    if (g_is64) return (int)((const long long*)ei)[idx];
    return ((const int*)ei)[idx];
}

// ---------------- CSR build ----------------
__global__ void zero_cnt_k() {
    int i = blockIdx.x * blockDim.x + threadIdx.x;
    if (i < NN) g_cnt[i] = 0;
}

__global__ void count_k(const void* __restrict__ ei, int E) {
    int e = blockIdx.x * blockDim.x + threadIdx.x;
    if (e < E) {
        int dst = edge_val(ei, (long long)E + e);
        atomicAdd(&g_cnt[dst], 1);
    }
}

// multi-block scan: 98 blocks x 512
__global__ void scan1_k() {
    __shared__ int red[512];
    int t = threadIdx.x;
    int i = blockIdx.x * 512 + t;
    red[t] = (i < NN) ? g_cnt[i] : 0;
    __syncthreads();
    for (int off = 256; off > 0; off >>= 1) {
        if (t < off) red[t] += red[t + off];
        __syncthreads();
    }
    if (t == 0) g_bsum[blockIdx.x] = red[0];
}

__global__ void scan2_k(int nb) {
    __shared__ int s[128];
    int t = threadIdx.x;
    int own = (t < nb) ? g_bsum[t] : 0;
    s[t] = own;
    __syncthreads();
    for (int off = 1; off < 128; off <<= 1) {
        int v = (t >= off) ? s[t - off] : 0;
        __syncthreads();
        s[t] += v;
        __syncthreads();
    }
    if (t < nb) g_boff[t] = s[t] - own;   // exclusive
}

__global__ void scan3_k() {
    __shared__ int s[512];
    int t = threadIdx.x;
    int i = blockIdx.x * 512 + t;
    int own = (i < NN) ? g_cnt[i] : 0;
    s[t] = own;
    __syncthreads();
    for (int off = 1; off < 512; off <<= 1) {
        int v = (t >= off) ? s[t - off] : 0;
        __syncthreads();
        s[t] += v;
        __syncthreads();
    }
    int boff = g_boff[blockIdx.x];
    if (i < NN) {
        int excl = s[t] - own + boff;
        g_rowptr[i] = excl;
        g_cursor[i] = excl;
        if (i == NN - 1) g_rowptr[NN] = s[t] + boff;
    }
}

__global__ void fill_k(const void* __restrict__ ei, int E) {
    int e = blockIdx.x * blockDim.x + threadIdx.x;
    if (e < E) {
        int dst = edge_val(ei, (long long)E + e);
        int src = edge_val(ei, e);
        int pos = atomicAdd(&g_cursor[dst], 1);
        g_col[pos] = src;
    }
}

// ---------------- bf16x3 WMMA triple GEMM ----------------
// C[M,128] = prologue(A)[M,128] @ B[128,128]
// prologue: optional per-column BN scale/shift + LeakyReLU (fused from prev layer)
// fp32 operands split into bf16 hi+lo; C += Ah*Bh + Ah*Bl + Al*Bh (fp32 accum).
// Block: 256 threads (8 warps, 4x2 warp grid), tile 128x128, K chunks of 32.
// blockIdx.x selects (B,O) among up to 3; blockIdx.y = row block.
// Output arrays are padded to NP rows -> unguarded stores.
__global__ void __launch_bounds__(256) gemm3_k(
    const float* __restrict__ A,
    const float* __restrict__ B0, const float* __restrict__ B1, const float* __restrict__ B2,
    float* __restrict__ O0, float* __restrict__ O1, float* __restrict__ O2,
    int M, int bnmode)
{
    const float* B = (blockIdx.x == 0) ? B0 : (blockIdx.x == 1) ? B1 : B2;
    float* O       = (blockIdx.x == 0) ? O0 : (blockIdx.x == 1) ? O1 : O2;

    __shared__ __nv_bfloat16 Ah[128][40];
    __shared__ __nv_bfloat16 Al[128][40];
    __shared__ __nv_bfloat16 Bh[32][136];
    __shared__ __nv_bfloat16 Bl[32][136];
    __shared__ float ssc[128];
    __shared__ float ssh[128];

    int t = threadIdx.x;
    int row0 = blockIdx.y * 128;

    if (t < 128) {
        ssc[t] = g_bnsc[t];
        ssh[t] = g_bnsh[t];
    }
    __syncthreads();

    int wid = t >> 5;
    int wm = wid >> 1;   // 0..3
    int wn = wid & 1;    // 0..1

    wmma::fragment<wmma::accumulator, 16, 16, 16, float> acc[2][4];
#pragma unroll
    for (int i = 0; i < 2; i++)
#pragma unroll
        for (int j = 0; j < 4; j++) wmma::fill_fragment(acc[i][j], 0.0f);

    for (int k0 = 0; k0 < 128; k0 += 32) {
        // load A chunk 128x32 (4 float4 per thread), BN prologue, split
#pragma unroll
        for (int q4 = 0; q4 < 4; q4++) {
            int q = t * 4 + q4;          // 0..1023
            int r = q >> 3;              // 0..127
            int c = (q & 7) * 4;         // 0,4,...,28
            float4 v;
            int gr = row0 + r;
            if (gr < M)
                v = *(const float4*)&A[(size_t)gr * 128 + k0 + c];
            else
                v = make_float4(0.f, 0.f, 0.f, 0.f);
            float vv[4] = {v.x, v.y, v.z, v.w};
#pragma unroll
            for (int j = 0; j < 4; j++) {
                float x = vv[j];
                if (bnmode) {
                    x = x * ssc[k0 + c + j] + ssh[k0 + c + j];
                    x = (x > 0.f) ? x : SLOPE * x;
                }
                __nv_bfloat16 hi = __float2bfloat16(x);
                float rem = x - __bfloat162float(hi);
                Ah[r][c + j] = hi;
                Al[r][c + j] = __float2bfloat16(rem);
            }
        }
        // load B chunk 32x128 (4 float4 per thread), split
#pragma unroll
        for (int q4 = 0; q4 < 4; q4++) {
            int q = t * 4 + q4;
            int r = q >> 5;              // 0..31
            int c = (q & 31) * 4;        // 0..124
            float4 v = *(const float4*)&B[(size_t)(k0 + r) * 128 + c];
            float vv[4] = {v.x, v.y, v.z, v.w};
#pragma unroll
            for (int j = 0; j < 4; j++) {
                float x = vv[j];
                __nv_bfloat16 hi = __float2bfloat16(x);
                float rem = x - __bfloat162float(hi);
                Bh[r][c + j] = hi;
                Bl[r][c + j] = __float2bfloat16(rem);
            }
        }
        __syncthreads();

#pragma unroll
        for (int kk = 0; kk < 32; kk += 16) {
            wmma::fragment<wmma::matrix_a, 16, 16, 16, __nv_bfloat16, wmma::row_major> ah[2], al[2];
#pragma unroll
            for (int m2 = 0; m2 < 2; m2++) {
                wmma::load_matrix_sync(ah[m2], &Ah[wm * 32 + m2 * 16][kk], 40);
                wmma::load_matrix_sync(al[m2], &Al[wm * 32 + m2 * 16][kk], 40);
            }
#pragma unroll
            for (int n = 0; n < 4; n++) {
                wmma::fragment<wmma::matrix_b, 16, 16, 16, __nv_bfloat16, wmma::row_major> bh, bl;
                wmma::load_matrix_sync(bh, &Bh[kk][wn * 64 + n * 16], 136);
                wmma::load_matrix_sync(bl, &Bl[kk][wn * 64 + n * 16], 136);
#pragma unroll
                for (int m2 = 0; m2 < 2; m2++) {
                    wmma::mma_sync(acc[m2][n], ah[m2], bh, acc[m2][n]);
                    wmma::mma_sync(acc[m2][n], ah[m2], bl, acc[m2][n]);
                    wmma::mma_sync(acc[m2][n], al[m2], bh, acc[m2][n]);
                }
            }
        }
        __syncthreads();
    }

#pragma unroll
    for (int m2 = 0; m2 < 2; m2++)
#pragma unroll
        for (int n = 0; n < 4; n++) {
            int gr = row0 + wm * 32 + m2 * 16;
            int gc = wn * 64 + n * 16;
            wmma::store_matrix_sync(&O[(size_t)gr * 128 + gc], acc[m2][n], 128, wmma::mem_row_major);
        }
}

// ---------------- fused GATv2 per-node kernel ----------------
__global__ void gat_node_k(const float* __restrict__ xl, const float* __restrict__ xr,
                           const float* __restrict__ xres, const float* __restrict__ bias,
                           const float* __restrict__ att, float* __restrict__ out)
{
    int v = blockIdx.x;
    int t = threadIdx.x;

    float xrv = xr[(size_t)v * DD + t];
    float a   = att[t];

    float denom = 0.f, acc = 0.f;

    // self loop
    {
        float m = xl[(size_t)v * DD + t];
        float p = m + xrv;
        p = (p > 0.f) ? p : SLOPE * p;
        float sc = p * a;
#pragma unroll
        for (int o = 16; o > 0; o >>= 1)
            sc += __shfl_xor_sync(0xffffffffu, sc, o);
        float w = __expf(sc);
        denom += w;
        acc += w * m;
    }

    int j = g_rowptr[v];
    int e2 = g_rowptr[v + 1];
    for (; j + 2 <= e2; j += 2) {
        int s0 = g_col[j];
        int s1 = g_col[j + 1];
        float m0 = xl[(size_t)s0 * DD + t];
        float m1 = xl[(size_t)s1 * DD + t];
        float p0 = m0 + xrv; p0 = (p0 > 0.f) ? p0 : SLOPE * p0;
        float p1 = m1 + xrv; p1 = (p1 > 0.f) ? p1 : SLOPE * p1;
        float sc0 = p0 * a;
        float sc1 = p1 * a;
#pragma unroll
        for (int o = 16; o > 0; o >>= 1) {
            sc0 += __shfl_xor_sync(0xffffffffu, sc0, o);
            sc1 += __shfl_xor_sync(0xffffffffu, sc1, o);
        }
        float w0 = __expf(sc0);
        float w1 = __expf(sc1);
        denom += w0 + w1;
        acc = fmaf(w0, m0, acc);
        acc = fmaf(w1, m1, acc);
    }
    if (j < e2) {
        int s0 = g_col[j];
        float m0 = xl[(size_t)s0 * DD + t];
        float p0 = m0 + xrv; p0 = (p0 > 0.f) ? p0 : SLOPE * p0;
        float sc0 = p0 * a;
#pragma unroll
        for (int o = 16; o > 0; o >>= 1)
            sc0 += __shfl_xor_sync(0xffffffffu, sc0, o);
        float w0 = __expf(sc0);
        denom += w0;
        acc = fmaf(w0, m0, acc);
    }

    out[(size_t)v * DD + t] = acc / denom + bias[t] + xres[(size_t)v * DD + t];
}

// ---------------- BatchNorm (stats only; apply fused into next GEMM) ----------------
__global__ void bn_zero_k() {
    int t = threadIdx.x;
    if (t < DD) { g_sum[t] = 0.0; g_sumsq[t] = 0.0; }
}

__global__ void bn_stats_k(const float* __restrict__ x) {
    int t = threadIdx.x;                    // column
    int rows = (NN + gridDim.x - 1) / gridDim.x;
    int r0 = blockIdx.x * rows;
    int r1 = min(NN, r0 + rows);
    float s = 0.f, ss = 0.f;
    for (int r = r0; r < r1; r++) {
        float v = x[(size_t)r * DD + t];
        s += v;
        ss = fmaf(v, v, ss);
    }
    atomicAdd(&g_sum[t], (double)s);
    atomicAdd(&g_sumsq[t], (double)ss);
}

__global__ void bn_final_k(const float* __restrict__ gamma, const float* __restrict__ beta) {
    int t = threadIdx.x;
    double mu = g_sum[t] / (double)NN;
    double var = g_sumsq[t] / (double)NN - mu * mu;
    float sc = (float)(1.0 / sqrt(var + BN_EPS)) * gamma[t];
    g_bnsc[t] = sc;
    g_bnsh[t] = beta[t] - (float)mu * sc;
}

// ---------------- final bias add + copy to output ----------------
__global__ void bias_copy_k(const float* __restrict__ in, const float* __restrict__ bias,
                            float* __restrict__ out)
{
    int i = blockIdx.x * blockDim.x + threadIdx.x;   // float4 index
    if (i < NN * 32) {
        float4 v = ((const float4*)in)[i];
        int c = (i & 31) * 4;
        v.x += bias[c + 0];
        v.y += bias[c + 1];
        v.z += bias[c + 2];
        v.w += bias[c + 3];
        ((float4*)out)[i] = v;
    }
}

// ---------------- launch ----------------
extern "C" void kernel_launch(void* const* d_in, const int* in_sizes, int n_in,
                              void* d_out, int out_size)
{
    const float* x     = (const float*)d_in[0];
    const void*  ei    = (const void*)d_in[1];
    const float* Wl    = (const float*)d_in[2];
    const float* Wr    = (const float*)d_in[3];
    const float* att   = (const float*)d_in[4];
    const float* bias  = (const float*)d_in[5];
    const float* Wres  = (const float*)d_in[6];
    const float* gamma = (const float*)d_in[7];
    const float* beta  = (const float*)d_in[8];
    const float* Wout  = (const float*)d_in[9];
    const float* bout  = (const float*)d_in[10];
    float* out = (float*)d_out;

    int E = in_sizes[1] / 2;

    float *xl, *xr, *xres, *h;
    cudaGetSymbolAddress((void**)&xl,   g_xl);
    cudaGetSymbolAddress((void**)&xr,   g_xr);
    cudaGetSymbolAddress((void**)&xres, g_xres);
    cudaGetSymbolAddress((void**)&h,    g_h);

    // dtype sniff + CSR build (reused by all 3 layers)
    detect_dtype_k<<<1, 32>>>((const unsigned int*)ei);
    zero_cnt_k<<<(NN + 255) / 256, 256>>>();
    count_k<<<(E + 255) / 256, 256>>>(ei, E);
    int nb = (NN + 511) / 512;   // 98
    scan1_k<<<nb, 512>>>();
    scan2_k<<<1, 128>>>(nb);
    scan3_k<<<nb, 512>>>();
    fill_k<<<(E + 255) / 256, 256>>>(ei, E);

    dim3 g3(3, NP / 128);   // (3, 391)
    dim3 g1(1, NP / 128);

    const float* xin = x;
    for (int i = 0; i < LL; i++) {
        int bnmode = (i > 0) ? 1 : 0;
        gemm3_k<<<g3, 256>>>(xin,
                             Wl + (size_t)i * DD * DD, Wr + (size_t)i * DD * DD,
                             Wres + (size_t)i * DD * DD,
                             xl, xr, xres, NN, bnmode);
        gat_node_k<<<NN, 128>>>(xl, xr, xres, bias + (size_t)i * DD,
                                att + (size_t)i * HH * CC, h);
        bn_zero_k<<<1, DD>>>();
        bn_stats_k<<<400, DD>>>(h);
        bn_final_k<<<1, DD>>>(gamma + (size_t)i * DD, beta + (size_t)i * DD);
        xin = h;
    }

    // final linear: BN+leaky prologue on h, result to scratch, then bias-add copy
    gemm3_k<<<g1, 256>>>(h, Wout, nullptr, nullptr, xl, nullptr, nullptr, NN, 1);
    bias_copy_k<<<(NN * 32 + 255) / 256, 256>>>(xl, bout, out);
}

// round 6
// speedup vs baseline: 1.5986x; 1.1981x over previous
#include <cuda_runtime.h>
#include <cuda_bf16.h>
#include <mma.h>
#include <math.h>
#include <stdint.h>

using namespace nvcuda;

#define NN 50000
#define NP 50048            // padded rows: 391 * 128
#define DD 128
#define HH 4
#define CC 32
#define LL 3
#define EE 800000
#define SLOPE 0.2f
#define BN_EPS 1e-5

// ---------------- scratch (static device globals; no allocation) ----------------
__device__ float g_xl[NP * DD];
__device__ float g_xr[NP * DD];
__device__ float g_xres[NP * DD];
__device__ float g_h[NP * DD];
__device__ __nv_bfloat16 g_ah[NP * DD];      // A hi split (bf16)
__device__ __nv_bfloat16 g_al[NP * DD];      // A lo split
__device__ __nv_bfloat16 g_wh[3 * DD * DD];  // W hi split (up to 3 mats)
__device__ __nv_bfloat16 g_wl[3 * DD * DD];
__device__ int   g_rowptr[NN + 1];
__device__ int   g_cursor[NN];
__device__ int   g_cnt[NN];
__device__ int   g_col[EE];
__device__ int   g_bsum[128];
__device__ int   g_boff[128];
__device__ double g_sum[DD];
__device__ double g_sumsq[DD];
__device__ float g_bnsc[DD];
__device__ float g_bnsh[DD];
__device__ int   g_is64;

__device__ __forceinline__ uint32_t pack_bf2(__nv_bfloat16 a, __nv_bfloat16 b) {
    __nv_bfloat162 p;
    p.x = a; p.y = b;
    return *(uint32_t*)&p;
}

// ---------------- edge_index dtype detection ----------------
__global__ void detect_dtype_k(const unsigned int* __restrict__ w) {
    if (threadIdx.x == 0 && blockIdx.x == 0) {
        int is64 = 1;
        for (int i = 1; i < 64; i += 2)
            if (w[i] != 0u) { is64 = 0; break; }
        g_is64 = is64;
    }
}

__device__ __forceinline__ int edge_val(const void* ei, long long idx) {
    if (g_is64) return (int)((const long long*)ei)[idx];
    return ((const int*)ei)[idx];
}

// ---------------- CSR build ----------------
__global__ void zero_cnt_k() {
    int i = blockIdx.x * blockDim.x + threadIdx.x;
    if (i < NN) g_cnt[i] = 0;
}

__global__ void count_k(const void* __restrict__ ei, int E) {
    int e = blockIdx.x * blockDim.x + threadIdx.x;
    if (e < E) {
        int dst = edge_val(ei, (long long)E + e);
        atomicAdd(&g_cnt[dst], 1);
    }
}

__global__ void scan1_k() {
    __shared__ int red[512];
    int t = threadIdx.x;
    int i = blockIdx.x * 512 + t;
    red[t] = (i < NN) ? g_cnt[i] : 0;
    __syncthreads();
    for (int off = 256; off > 0; off >>= 1) {
        if (t < off) red[t] += red[t + off];
        __syncthreads();
    }
    if (t == 0) g_bsum[blockIdx.x] = red[0];
}

__global__ void scan2_k(int nb) {
    __shared__ int s[128];
    int t = threadIdx.x;
    int own = (t < nb) ? g_bsum[t] : 0;
    s[t] = own;
    __syncthreads();
    for (int off = 1; off < 128; off <<= 1) {
        int v = (t >= off) ? s[t - off] : 0;
        __syncthreads();
        s[t] += v;
        __syncthreads();
    }
    if (t < nb) g_boff[t] = s[t] - own;
}

__global__ void scan3_k() {
    __shared__ int s[512];
    int t = threadIdx.x;
    int i = blockIdx.x * 512 + t;
    int own = (i < NN) ? g_cnt[i] : 0;
    s[t] = own;
    __syncthreads();
    for (int off = 1; off < 512; off <<= 1) {
        int v = (t >= off) ? s[t - off] : 0;
        __syncthreads();
        s[t] += v;
        __syncthreads();
    }
    int boff = g_boff[blockIdx.x];
    if (i < NN) {
        int excl = s[t] - own + boff;
        g_rowptr[i] = excl;
        g_cursor[i] = excl;
        if (i == NN - 1) g_rowptr[NN] = s[t] + boff;
    }
}

__global__ void fill_k(const void* __restrict__ ei, int E) {
    int e = blockIdx.x * blockDim.x + threadIdx.x;
    if (e < E) {
        int dst = edge_val(ei, (long long)E + e);
        int src = edge_val(ei, e);
        int pos = atomicAdd(&g_cursor[dst], 1);
        g_col[pos] = src;
    }
}

// ---------------- A-side conversion: BN affine + leaky + bf16 hi/lo split ----------------
__global__ void aconv_k(const float* __restrict__ X, int M, int bnmode) {
    int i = blockIdx.x * blockDim.x + threadIdx.x;   // float4 id
    if (i >= NP * 32) return;
    int row = i >> 5;
    int c = (i & 31) * 4;
    float4 v = make_float4(0.f, 0.f, 0.f, 0.f);
    if (row < M) v = ((const float4*)X)[i];
    float vv[4] = {v.x, v.y, v.z, v.w};
    __nv_bfloat16 hb[4], lb[4];
#pragma unroll
    for (int j = 0; j < 4; j++) {
        float x = vv[j];
        if (bnmode) {
            x = fmaf(x, g_bnsc[c + j], g_bnsh[c + j]);
            x = (x > 0.f) ? x : SLOPE * x;
        }
        hb[j] = __float2bfloat16(x);
        lb[j] = __float2bfloat16(x - __bfloat162float(hb[j]));
    }
    uint2 ph, pl;
    ph.x = pack_bf2(hb[0], hb[1]); ph.y = pack_bf2(hb[2], hb[3]);
    pl.x = pack_bf2(lb[0], lb[1]); pl.y = pack_bf2(lb[2], lb[3]);
    ((uint2*)g_ah)[i] = ph;
    ((uint2*)g_al)[i] = pl;
}

// ---------------- W conversion (kept [k][n] row-major for wmma matrix_b) ----------------
__global__ void wconv_k(const float* __restrict__ W0, const float* __restrict__ W1,
                        const float* __restrict__ W2) {
    int m = blockIdx.x;
    const float* W = (m == 0) ? W0 : (m == 1) ? W1 : W2;
    if (W == nullptr) return;
    int q = blockIdx.y * 256 + threadIdx.x;          // float4 id 0..4095
    float4 v = ((const float4*)W)[q];
    float vv[4] = {v.x, v.y, v.z, v.w};
    __nv_bfloat16 hb[4], lb[4];
#pragma unroll
    for (int j = 0; j < 4; j++) {
        float x = vv[j];
        hb[j] = __float2bfloat16(x);
        lb[j] = __float2bfloat16(x - __bfloat162float(hb[j]));
    }
    uint2 ph, pl;
    ph.x = pack_bf2(hb[0], hb[1]); ph.y = pack_bf2(hb[2], hb[3]);
    pl.x = pack_bf2(lb[0], lb[1]); pl.y = pack_bf2(lb[2], lb[3]);
    ((uint2*)g_wh)[m * 4096 + q] = ph;
    ((uint2*)g_wl)[m * 4096 + q] = pl;
}

// ---------------- pure-bf16 WMMA triple GEMM ----------------
// C[M,128] = A[M,128] @ W[128,128]; A/W pre-split into bf16 hi/lo in global.
// 3 terms: Ah*Bh + Al*Bh + Ah*Bl with fp32 accumulators.
// Block 256 thr (8 warps, 4x2), tile 128x128, K chunks of 64.
#define GA_STR 72     // A smem stride (elements)
#define GB_STR 136    // B smem stride
#define SM_AH  0
#define SM_AL  (128 * GA_STR * 2)                 // 18432
#define SM_BH  (SM_AL + 128 * GA_STR * 2)         // 36864
#define SM_BL  (SM_BH + 64 * GB_STR * 2)          // 54272
#define SM_SZ  (SM_BL + 64 * GB_STR * 2)          // 71680

__global__ void __launch_bounds__(256) gemm_k(
    float* __restrict__ O0, float* __restrict__ O1, float* __restrict__ O2,
    int rowbase)
{
    extern __shared__ char smem[];
    __nv_bfloat16* sAh = (__nv_bfloat16*)(smem + SM_AH);
    __nv_bfloat16* sAl = (__nv_bfloat16*)(smem + SM_AL);
    __nv_bfloat16* sBh = (__nv_bfloat16*)(smem + SM_BH);
    __nv_bfloat16* sBl = (__nv_bfloat16*)(smem + SM_BL);

    int t = threadIdx.x;
    int wid = t >> 5;
    int wm = wid >> 1;   // 0..3
    int wn = wid & 1;    // 0..1
    int row0 = (blockIdx.y + rowbase) * 128;
    int mat = blockIdx.x;
    float* O = (mat == 0) ? O0 : (mat == 1) ? O1 : O2;
    const __nv_bfloat16* Wh = g_wh + (size_t)mat * DD * DD;
    const __nv_bfloat16* Wl_ = g_wl + (size_t)mat * DD * DD;

    wmma::fragment<wmma::accumulator, 16, 16, 16, float> acc[2][4];
#pragma unroll
    for (int i = 0; i < 2; i++)
#pragma unroll
        for (int j = 0; j < 4; j++) wmma::fill_fragment(acc[i][j], 0.0f);

    for (int k0 = 0; k0 < 128; k0 += 64) {
        // A chunk: 128 rows x 64 cols, hi+lo. 1024 uint4 per term, 4/thread.
#pragma unroll
        for (int g = 0; g < 4; g++) {
            int idx = t + 256 * g;
            int r = idx >> 3;
            int c8 = (idx & 7) * 8;
            size_t go = (size_t)(row0 + r) * 128 + k0 + c8;
            *(uint4*)&sAh[r * GA_STR + c8] = *(const uint4*)&g_ah[go];
            *(uint4*)&sAl[r * GA_STR + c8] = *(const uint4*)&g_al[go];
        }
        // B chunk: 64 rows x 128 cols, hi+lo.
#pragma unroll
        for (int g = 0; g < 4; g++) {
            int idx = t + 256 * g;
            int r = idx >> 4;
            int c8 = (idx & 15) * 8;
            size_t go = (size_t)(k0 + r) * 128 + c8;
            *(uint4*)&sBh[r * GB_STR + c8] = *(const uint4*)&Wh[go];
            *(uint4*)&sBl[r * GB_STR + c8] = *(const uint4*)&Wl_[go];
        }
        __syncthreads();

#pragma unroll
        for (int kk = 0; kk < 64; kk += 16) {
            wmma::fragment<wmma::matrix_a, 16, 16, 16, __nv_bfloat16, wmma::row_major> ah[2], al[2];
#pragma unroll
            for (int m2 = 0; m2 < 2; m2++) {
                wmma::load_matrix_sync(ah[m2], &sAh[(wm * 32 + m2 * 16) * GA_STR + kk], GA_STR);
                wmma::load_matrix_sync(al[m2], &sAl[(wm * 32 + m2 * 16) * GA_STR + kk], GA_STR);
            }
#pragma unroll
            for (int n = 0; n < 4; n++) {
                wmma::fragment<wmma::matrix_b, 16, 16, 16, __nv_bfloat16, wmma::row_major> bh, bl;
                wmma::load_matrix_sync(bh, &sBh[kk * GB_STR + wn * 64 + n * 16], GB_STR);
                wmma::load_matrix_sync(bl, &sBl[kk * GB_STR + wn * 64 + n * 16], GB_STR);
#pragma unroll
                for (int m2 = 0; m2 < 2; m2++) {
                    wmma::mma_sync(acc[m2][n], ah[m2], bh, acc[m2][n]);
                    wmma::mma_sync(acc[m2][n], ah[m2], bl, acc[m2][n]);
                    wmma::mma_sync(acc[m2][n], al[m2], bh, acc[m2][n]);
                }
            }
        }
        __syncthreads();
    }

#pragma unroll
    for (int m2 = 0; m2 < 2; m2++)
#pragma unroll
        for (int n = 0; n < 4; n++) {
            int gr = row0 + wm * 32 + m2 * 16;
            int gc = wn * 64 + n * 16;
            wmma::store_matrix_sync(&O[(size_t)gr * 128 + gc], acc[m2][n], 128, wmma::mem_row_major);
        }
}

// ---------------- fused GATv2 per-node kernel ----------------
__global__ void gat_node_k(const float* __restrict__ xl, const float* __restrict__ xr,
                           const float* __restrict__ xres, const float* __restrict__ bias,
                           const float* __restrict__ att, float* __restrict__ out)
{
    int v = blockIdx.x;
    int t = threadIdx.x;

    float xrv = xr[(size_t)v * DD + t];
    float a   = att[t];

    float denom = 0.f, acc = 0.f;

    {
        float m = xl[(size_t)v * DD + t];
        float p = m + xrv;
        p = (p > 0.f) ? p : SLOPE * p;
        float sc = p * a;
#pragma unroll
        for (int o = 16; o > 0; o >>= 1)
            sc += __shfl_xor_sync(0xffffffffu, sc, o);
        float w = __expf(sc);
        denom += w;
        acc += w * m;
    }

    int j = g_rowptr[v];
    int e2 = g_rowptr[v + 1];
    for (; j + 2 <= e2; j += 2) {
        int s0 = g_col[j];
        int s1 = g_col[j + 1];
        float m0 = xl[(size_t)s0 * DD + t];
        float m1 = xl[(size_t)s1 * DD + t];
        float p0 = m0 + xrv; p0 = (p0 > 0.f) ? p0 : SLOPE * p0;
        float p1 = m1 + xrv; p1 = (p1 > 0.f) ? p1 : SLOPE * p1;
        float sc0 = p0 * a;
        float sc1 = p1 * a;
#pragma unroll
        for (int o = 16; o > 0; o >>= 1) {
            sc0 += __shfl_xor_sync(0xffffffffu, sc0, o);
            sc1 += __shfl_xor_sync(0xffffffffu, sc1, o);
        }
        float w0 = __expf(sc0);
        float w1 = __expf(sc1);
        denom += w0 + w1;
        acc = fmaf(w0, m0, acc);
        acc = fmaf(w1, m1, acc);
    }
    if (j < e2) {
        int s0 = g_col[j];
        float m0 = xl[(size_t)s0 * DD + t];
        float p0 = m0 + xrv; p0 = (p0 > 0.f) ? p0 : SLOPE * p0;
        float sc0 = p0 * a;
#pragma unroll
        for (int o = 16; o > 0; o >>= 1)
            sc0 += __shfl_xor_sync(0xffffffffu, sc0, o);
        float w0 = __expf(sc0);
        denom += w0;
        acc = fmaf(w0, m0, acc);
    }

    out[(size_t)v * DD + t] = acc / denom + bias[t] + xres[(size_t)v * DD + t];
}

// ---------------- BatchNorm (stats only; apply fused into aconv) ----------------
__global__ void bn_zero_k() {
    int t = threadIdx.x;
    if (t < DD) { g_sum[t] = 0.0; g_sumsq[t] = 0.0; }
}

__global__ void bn_stats_k(const float* __restrict__ x) {
    int t = threadIdx.x;
    int rows = (NN + gridDim.x - 1) / gridDim.x;
    int r0 = blockIdx.x * rows;
    int r1 = min(NN, r0 + rows);
    float s = 0.f, ss = 0.f;
    for (int r = r0; r < r1; r++) {
        float v = x[(size_t)r * DD + t];
        s += v;
        ss = fmaf(v, v, ss);
    }
    atomicAdd(&g_sum[t], (double)s);
    atomicAdd(&g_sumsq[t], (double)ss);
}

__global__ void bn_final_k(const float* __restrict__ gamma, const float* __restrict__ beta) {
    int t = threadIdx.x;
    double mu = g_sum[t] / (double)NN;
    double var = g_sumsq[t] / (double)NN - mu * mu;
    float sc = (float)(1.0 / sqrt(var + BN_EPS)) * gamma[t];
    g_bnsc[t] = sc;
    g_bnsh[t] = beta[t] - (float)mu * sc;
}

// ---------------- final bias add + copy to output ----------------
__global__ void bias_copy_k(const float* __restrict__ in, const float* __restrict__ bias,
                            float* __restrict__ out)
{
    int i = blockIdx.x * blockDim.x + threadIdx.x;
    if (i < NN * 32) {
        float4 v = ((const float4*)in)[i];
        int c = (i & 31) * 4;
        v.x += bias[c + 0];
        v.y += bias[c + 1];
        v.z += bias[c + 2];
        v.w += bias[c + 3];
        ((float4*)out)[i] = v;
    }
}

// ---------------- launch ----------------
extern "C" void kernel_launch(void* const* d_in, const int* in_sizes, int n_in,
                              void* d_out, int out_size)
{
    const float* x     = (const float*)d_in[0];
    const void*  ei    = (const void*)d_in[1];
    const float* Wl    = (const float*)d_in[2];
    const float* Wr    = (const float*)d_in[3];
    const float* att   = (const float*)d_in[4];
    const float* bias  = (const float*)d_in[5];
    const float* Wres  = (const float*)d_in[6];
    const float* gamma = (const float*)d_in[7];
    const float* beta  = (const float*)d_in[8];
    const float* Wout  = (const float*)d_in[9];
    const float* bout  = (const float*)d_in[10];
    float* out = (float*)d_out;

    int E = in_sizes[1] / 2;

    float *xl, *xr, *xres, *h;
    cudaGetSymbolAddress((void**)&xl,   g_xl);
    cudaGetSymbolAddress((void**)&xr,   g_xr);
    cudaGetSymbolAddress((void**)&xres, g_xres);
    cudaGetSymbolAddress((void**)&h,    g_h);

    cudaFuncSetAttribute(gemm_k, cudaFuncAttributeMaxDynamicSharedMemorySize, SM_SZ);

    const int ACONV_G = (NP * 32) / 256;   // 6256
    dim3 wg3(3, 16);
    dim3 wg1(1, 16);
    dim3 gg3(3, NP / 128);

    // layer-0 GEMM pipeline first (positions ~4-5 for ncu capture window)
    detect_dtype_k<<<1, 32>>>((const unsigned int*)ei);
    aconv_k<<<ACONV_G, 256>>>(x, NN, 0);
    wconv_k<<<wg3, 256>>>(Wl, Wr, Wres);
    gemm_k<<<dim3(3, 196), 256, SM_SZ>>>(xl, xr, xres, 0);
    gemm_k<<<dim3(3, 195), 256, SM_SZ>>>(xl, xr, xres, 196);

    // CSR build
    zero_cnt_k<<<(NN + 255) / 256, 256>>>();
    count_k<<<(E + 255) / 256, 256>>>(ei, E);
    int nb = (NN + 511) / 512;
    scan1_k<<<nb, 512>>>();
    scan2_k<<<1, 128>>>(nb);
    scan3_k<<<nb, 512>>>();
    fill_k<<<(E + 255) / 256, 256>>>(ei, E);

    for (int i = 0; i < LL; i++) {
        if (i > 0) {
            aconv_k<<<ACONV_G, 256>>>(h, NN, 1);
            wconv_k<<<wg3, 256>>>(Wl + (size_t)i * DD * DD, Wr + (size_t)i * DD * DD,
                                  Wres + (size_t)i * DD * DD);
            gemm_k<<<gg3, 256, SM_SZ>>>(xl, xr, xres, 0);
        }
        gat_node_k<<<NN, 128>>>(xl, xr, xres, bias + (size_t)i * DD,
                                att + (size_t)i * HH * CC, h);
        bn_zero_k<<<1, DD>>>();
        bn_stats_k<<<400, DD>>>(h);
        bn_final_k<<<1, DD>>>(gamma + (size_t)i * DD, beta + (size_t)i * DD);
    }

    // final linear
    aconv_k<<<ACONV_G, 256>>>(h, NN, 1);
    wconv_k<<<wg1, 256>>>(Wout, nullptr, nullptr);
    gemm_k<<<dim3(1, NP / 128), 256, SM_SZ>>>(xl, nullptr, nullptr, 0);
    bias_copy_k<<<(NN * 32 + 255) / 256, 256>>>(xl, bout, out);
}

// round 7
// speedup vs baseline: 2.2703x; 1.4202x over previous
#include <cuda_runtime.h>
#include <cuda_bf16.h>
#include <mma.h>
#include <math.h>
#include <stdint.h>

using namespace nvcuda;

#define NN 50000
#define NP 50048            // padded rows: 391 * 128
#define DD 128
#define HH 4
#define CC 32
#define LL 3
#define EE 800000
#define SLOPE 0.2f
#define BN_EPS 1e-5

// ---------------- scratch (static device globals; no allocation) ----------------
__device__ float g_xl[NP * DD];
__device__ float g_xr[NP * DD];
__device__ float g_xres[NP * DD];
__device__ float g_h[NP * DD];
__device__ __nv_bfloat16 g_ah[NP * DD];      // A hi split (bf16)
__device__ __nv_bfloat16 g_al[NP * DD];      // A lo split
__device__ __nv_bfloat16 g_wh[3 * DD * DD];  // W hi split (up to 3 mats)
__device__ __nv_bfloat16 g_wl[3 * DD * DD];
__device__ int   g_rowptr[NN + 1];
__device__ int   g_cursor[NN];
__device__ int   g_cnt[NN];
__device__ int   g_col[EE];
__device__ int   g_bsum[128];
__device__ int   g_boff[128];
__device__ double g_sum[DD];
__device__ double g_sumsq[DD];
__device__ float g_bnsc[DD];
__device__ float g_bnsh[DD];
__device__ int   g_is64;

__device__ __forceinline__ uint32_t pack_bf2(__nv_bfloat16 a, __nv_bfloat16 b) {
    __nv_bfloat162 p;
    p.x = a; p.y = b;
    return *(uint32_t*)&p;
}

// ---------------- edge_index dtype detection ----------------
__global__ void detect_dtype_k(const unsigned int* __restrict__ w) {
    if (threadIdx.x == 0 && blockIdx.x == 0) {
        int is64 = 1;
        for (int i = 1; i < 64; i += 2)
            if (w[i] != 0u) { is64 = 0; break; }
        g_is64 = is64;
    }
}

__device__ __forceinline__ int edge_val(const void* ei, long long idx) {
    if (g_is64) return (int)((const long long*)ei)[idx];
    return ((const int*)ei)[idx];
}

// ---------------- CSR build ----------------
__global__ void zero_cnt_k() {
    int i = blockIdx.x * blockDim.x + threadIdx.x;
    if (i < NN) g_cnt[i] = 0;
}

__global__ void count_k(const void* __restrict__ ei, int E) {
    int e = blockIdx.x * blockDim.x + threadIdx.x;
    if (e < E) {
        int dst = edge_val(ei, (long long)E + e);
        atomicAdd(&g_cnt[dst], 1);
    }
}

__global__ void scan1_k() {
    __shared__ int red[512];
    int t = threadIdx.x;
    int i = blockIdx.x * 512 + t;
    red[t] = (i < NN) ? g_cnt[i] : 0;
    __syncthreads();
    for (int off = 256; off > 0; off >>= 1) {
        if (t < off) red[t] += red[t + off];
        __syncthreads();
    }
    if (t == 0) g_bsum[blockIdx.x] = red[0];
}

__global__ void scan2_k(int nb) {
    __shared__ int s[128];
    int t = threadIdx.x;
    int own = (t < nb) ? g_bsum[t] : 0;
    s[t] = own;
    __syncthreads();
    for (int off = 1; off < 128; off <<= 1) {
        int v = (t >= off) ? s[t - off] : 0;
        __syncthreads();
        s[t] += v;
        __syncthreads();
    }
    if (t < nb) g_boff[t] = s[t] - own;
}

__global__ void scan3_k() {
    __shared__ int s[512];
    int t = threadIdx.x;
    int i = blockIdx.x * 512 + t;
    int own = (i < NN) ? g_cnt[i] : 0;
    s[t] = own;
    __syncthreads();
    for (int off = 1; off < 512; off <<= 1) {
        int v = (t >= off) ? s[t - off] : 0;
        __syncthreads();
        s[t] += v;
        __syncthreads();
    }
    int boff = g_boff[blockIdx.x];
    if (i < NN) {
        int excl = s[t] - own + boff;
        g_rowptr[i] = excl;
        g_cursor[i] = excl;
        if (i == NN - 1) g_rowptr[NN] = s[t] + boff;
    }
}

__global__ void fill_k(const void* __restrict__ ei, int E) {
    int e = blockIdx.x * blockDim.x + threadIdx.x;
    if (e < E) {
        int dst = edge_val(ei, (long long)E + e);
        int src = edge_val(ei, e);
        int pos = atomicAdd(&g_cursor[dst], 1);
        g_col[pos] = src;
    }
}

// ---------------- A-side conversion: BN affine + leaky + bf16 hi/lo split ----------------
__global__ void aconv_k(const float* __restrict__ X, int M, int bnmode) {
    int i = blockIdx.x * blockDim.x + threadIdx.x;   // float4 id
    if (i >= NP * 32) return;
    int row = i >> 5;
    int c = (i & 31) * 4;
    float4 v = make_float4(0.f, 0.f, 0.f, 0.f);
    if (row < M) v = ((const float4*)X)[i];
    float vv[4] = {v.x, v.y, v.z, v.w};
    __nv_bfloat16 hb[4], lb[4];
#pragma unroll
    for (int j = 0; j < 4; j++) {
        float x = vv[j];
        if (bnmode) {
            x = fmaf(x, g_bnsc[c + j], g_bnsh[c + j]);
            x = (x > 0.f) ? x : SLOPE * x;
        }
        hb[j] = __float2bfloat16(x);
        lb[j] = __float2bfloat16(x - __bfloat162float(hb[j]));
    }
    uint2 ph, pl;
    ph.x = pack_bf2(hb[0], hb[1]); ph.y = pack_bf2(hb[2], hb[3]);
    pl.x = pack_bf2(lb[0], lb[1]); pl.y = pack_bf2(lb[2], lb[3]);
    ((uint2*)g_ah)[i] = ph;
    ((uint2*)g_al)[i] = pl;
}

// ---------------- W conversion (kept [k][n] row-major for wmma matrix_b) ----------------
__global__ void wconv_k(const float* __restrict__ W0, const float* __restrict__ W1,
                        const float* __restrict__ W2) {
    int m = blockIdx.x;
    const float* W = (m == 0) ? W0 : (m == 1) ? W1 : W2;
    if (W == nullptr) return;
    int q = blockIdx.y * 256 + threadIdx.x;          // float4 id 0..4095
    float4 v = ((const float4*)W)[q];
    float vv[4] = {v.x, v.y, v.z, v.w};
    __nv_bfloat16 hb[4], lb[4];
#pragma unroll
    for (int j = 0; j < 4; j++) {
        float x = vv[j];
        hb[j] = __float2bfloat16(x);
        lb[j] = __float2bfloat16(x - __bfloat162float(hb[j]));
    }
    uint2 ph, pl;
    ph.x = pack_bf2(hb[0], hb[1]); ph.y = pack_bf2(hb[2], hb[3]);
    pl.x = pack_bf2(lb[0], lb[1]); pl.y = pack_bf2(lb[2], lb[3]);
    ((uint2*)g_wh)[m * 4096 + q] = ph;
    ((uint2*)g_wl)[m * 4096 + q] = pl;
}

// ---------------- pure-bf16 WMMA triple GEMM ----------------
// C[M,128] = A[M,128] @ W[128,128]; A/W pre-split into bf16 hi/lo in global.
// 3 terms: Ah*Bh + Al*Bh + Ah*Bl with fp32 accumulators.
// Block 256 thr (8 warps, 4x2), tile 128x128, K chunks of 64.
// __launch_bounds__(256, 2): cap regs at 128 so 2 CTAs fit per SM (was 140 regs -> 1 CTA).
#define GA_STR 72     // A smem stride (elements)
#define GB_STR 136    // B smem stride
#define SM_AH  0
#define SM_AL  (128 * GA_STR * 2)                 // 18432
#define SM_BH  (SM_AL + 128 * GA_STR * 2)         // 36864
#define SM_BL  (SM_BH + 64 * GB_STR * 2)          // 54272
#define SM_SZ  (SM_BL + 64 * GB_STR * 2)          // 71680

__global__ void __launch_bounds__(256, 2) gemm_k(
    float* __restrict__ O0, float* __restrict__ O1, float* __restrict__ O2,
    int rowbase)
{
    extern __shared__ char smem[];
    __nv_bfloat16* sAh = (__nv_bfloat16*)(smem + SM_AH);
    __nv_bfloat16* sAl = (__nv_bfloat16*)(smem + SM_AL);
    __nv_bfloat16* sBh = (__nv_bfloat16*)(smem + SM_BH);
    __nv_bfloat16* sBl = (__nv_bfloat16*)(smem + SM_BL);

    int t = threadIdx.x;
    int wid = t >> 5;
    int wm = wid >> 1;   // 0..3
    int wn = wid & 1;    // 0..1
    int row0 = (blockIdx.y + rowbase) * 128;
    int mat = blockIdx.x;
    float* O = (mat == 0) ? O0 : (mat == 1) ? O1 : O2;
    const __nv_bfloat16* Wh = g_wh + (size_t)mat * DD * DD;
    const __nv_bfloat16* Wl_ = g_wl + (size_t)mat * DD * DD;

    wmma::fragment<wmma::accumulator, 16, 16, 16, float> acc[2][4];
#pragma unroll
    for (int i = 0; i < 2; i++)
#pragma unroll
        for (int j = 0; j < 4; j++) wmma::fill_fragment(acc[i][j], 0.0f);

    for (int k0 = 0; k0 < 128; k0 += 64) {
        // A chunk: 128 rows x 64 cols, hi+lo. 1024 uint4 per term, 4/thread.
#pragma unroll
        for (int g = 0; g < 4; g++) {
            int idx = t + 256 * g;
            int r = idx >> 3;
            int c8 = (idx & 7) * 8;
            size_t go = (size_t)(row0 + r) * 128 + k0 + c8;
            *(uint4*)&sAh[r * GA_STR + c8] = *(const uint4*)&g_ah[go];
            *(uint4*)&sAl[r * GA_STR + c8] = *(const uint4*)&g_al[go];
        }
        // B chunk: 64 rows x 128 cols, hi+lo.
#pragma unroll
        for (int g = 0; g < 4; g++) {
            int idx = t + 256 * g;
            int r = idx >> 4;
            int c8 = (idx & 15) * 8;
            size_t go = (size_t)(k0 + r) * 128 + c8;
            *(uint4*)&sBh[r * GB_STR + c8] = *(const uint4*)&Wh[go];
            *(uint4*)&sBl[r * GB_STR + c8] = *(const uint4*)&Wl_[go];
        }
        __syncthreads();

#pragma unroll
        for (int kk = 0; kk < 64; kk += 16) {
            wmma::fragment<wmma::matrix_a, 16, 16, 16, __nv_bfloat16, wmma::row_major> ah[2], al[2];
#pragma unroll
            for (int m2 = 0; m2 < 2; m2++) {
                wmma::load_matrix_sync(ah[m2], &sAh[(wm * 32 + m2 * 16) * GA_STR + kk], GA_STR);
                wmma::load_matrix_sync(al[m2], &sAl[(wm * 32 + m2 * 16) * GA_STR + kk], GA_STR);
            }
#pragma unroll
            for (int n = 0; n < 4; n++) {
                wmma::fragment<wmma::matrix_b, 16, 16, 16, __nv_bfloat16, wmma::row_major> bh, bl;
                wmma::load_matrix_sync(bh, &sBh[kk * GB_STR + wn * 64 + n * 16], GB_STR);
                wmma::load_matrix_sync(bl, &sBl[kk * GB_STR + wn * 64 + n * 16], GB_STR);
#pragma unroll
                for (int m2 = 0; m2 < 2; m2++) {
                    wmma::mma_sync(acc[m2][n], ah[m2], bh, acc[m2][n]);
                    wmma::mma_sync(acc[m2][n], ah[m2], bl, acc[m2][n]);
                    wmma::mma_sync(acc[m2][n], al[m2], bh, acc[m2][n]);
                }
            }
        }
        __syncthreads();
    }

#pragma unroll
    for (int m2 = 0; m2 < 2; m2++)
#pragma unroll
        for (int n = 0; n < 4; n++) {
            int gr = row0 + wm * 32 + m2 * 16;
            int gc = wn * 64 + n * 16;
            wmma::store_matrix_sync(&O[(size_t)gr * 128 + gc], acc[m2][n], 128, wmma::mem_row_major);
        }
}

// ---------------- fused GATv2: warp per node, float4 per lane ----------------
// Lane l owns channels 4l..4l+3 (head = l>>3). Per-head dot reduced with
// 3 shfl_xor (offsets 1,2,4) within the 8-lane head group; one __expf per lane.
__global__ void __launch_bounds__(256) gat_warp_k(
    const float* __restrict__ xl, const float* __restrict__ xr,
    const float* __restrict__ xres, const float* __restrict__ bias,
    const float* __restrict__ att, float* __restrict__ out)
{
    int warp = threadIdx.x >> 5;
    int lane = threadIdx.x & 31;
    int v = blockIdx.x * 8 + warp;          // 6250 * 8 == 50000, exact
    int c4 = lane * 4;

    float4 xrv = *(const float4*)&xr[(size_t)v * DD + c4];
    float4 a4  = *(const float4*)&att[c4];

    float denom = 0.f;
    float4 acc = make_float4(0.f, 0.f, 0.f, 0.f);

#define GAT_EDGE(SRC) do { \
        float4 m = *(const float4*)&xl[(size_t)(SRC) * DD + c4]; \
        float p0 = m.x + xrv.x; p0 = (p0 > 0.f) ? p0 : SLOPE * p0; \
        float p1 = m.y + xrv.y; p1 = (p1 > 0.f) ? p1 : SLOPE * p1; \
        float p2 = m.z + xrv.z; p2 = (p2 > 0.f) ? p2 : SLOPE * p2; \
        float p3 = m.w + xrv.w; p3 = (p3 > 0.f) ? p3 : SLOPE * p3; \
        float part = fmaf(p0, a4.x, fmaf(p1, a4.y, fmaf(p2, a4.z, p3 * a4.w))); \
        part += __shfl_xor_sync(0xffffffffu, part, 1); \
        part += __shfl_xor_sync(0xffffffffu, part, 2); \
        part += __shfl_xor_sync(0xffffffffu, part, 4); \
        float w = __expf(part); \
        denom += w; \
        acc.x = fmaf(w, m.x, acc.x); \
        acc.y = fmaf(w, m.y, acc.y); \
        acc.z = fmaf(w, m.z, acc.z); \
        acc.w = fmaf(w, m.w, acc.w); \
    } while (0)

    GAT_EDGE(v);   // self loop

    int j = g_rowptr[v];
    int e2 = g_rowptr[v + 1];
    for (; j + 2 <= e2; j += 2) {
        int s0 = g_col[j];
        int s1 = g_col[j + 1];
        GAT_EDGE(s0);
        GAT_EDGE(s1);
    }
    if (j < e2) {
        int s0 = g_col[j];
        GAT_EDGE(s0);
    }
#undef GAT_EDGE

    float inv = 1.f / denom;
    float4 b4 = *(const float4*)&bias[c4];
    float4 r4 = *(const float4*)&xres[(size_t)v * DD + c4];
    float4 o;
    o.x = fmaf(acc.x, inv, b4.x + r4.x);
    o.y = fmaf(acc.y, inv, b4.y + r4.y);
    o.z = fmaf(acc.z, inv, b4.z + r4.z);
    o.w = fmaf(acc.w, inv, b4.w + r4.w);
    *(float4*)&out[(size_t)v * DD + c4] = o;
}

// ---------------- BatchNorm (stats only; apply fused into aconv) ----------------
__global__ void bn_zero_k() {
    int t = threadIdx.x;
    if (t < DD) { g_sum[t] = 0.0; g_sumsq[t] = 0.0; }
}

__global__ void bn_stats_k(const float* __restrict__ x) {
    int t = threadIdx.x;
    int rows = (NN + gridDim.x - 1) / gridDim.x;
    int r0 = blockIdx.x * rows;
    int r1 = min(NN, r0 + rows);
    float s = 0.f, ss = 0.f;
    for (int r = r0; r < r1; r++) {
        float v = x[(size_t)r * DD + t];
        s += v;
        ss = fmaf(v, v, ss);
    }
    atomicAdd(&g_sum[t], (double)s);
    atomicAdd(&g_sumsq[t], (double)ss);
}

__global__ void bn_final_k(const float* __restrict__ gamma, const float* __restrict__ beta) {
    int t = threadIdx.x;
    double mu = g_sum[t] / (double)NN;
    double var = g_sumsq[t] / (double)NN - mu * mu;
    float sc = (float)(1.0 / sqrt(var + BN_EPS)) * gamma[t];
    g_bnsc[t] = sc;
    g_bnsh[t] = beta[t] - (float)mu * sc;
}

// ---------------- final bias add + copy to output ----------------
__global__ void bias_copy_k(const float* __restrict__ in, const float* __restrict__ bias,
                            float* __restrict__ out)
{
    int i = blockIdx.x * blockDim.x + threadIdx.x;
    if (i < NN * 32) {
        float4 v = ((const float4*)in)[i];
        int c = (i & 31) * 4;
        v.x += bias[c + 0];
        v.y += bias[c + 1];
        v.z += bias[c + 2];
        v.w += bias[c + 3];
        ((float4*)out)[i] = v;
    }
}

// ---------------- launch ----------------
extern "C" void kernel_launch(void* const* d_in, const int* in_sizes, int n_in,
                              void* d_out, int out_size)
{
    const float* x     = (const float*)d_in[0];
    const void*  ei    = (const void*)d_in[1];
    const float* Wl    = (const float*)d_in[2];
    const float* Wr    = (const float*)d_in[3];
    const float* att   = (const float*)d_in[4];
    const float* bias  = (const float*)d_in[5];
    const float* Wres  = (const float*)d_in[6];
    const float* gamma = (const float*)d_in[7];
    const float* beta  = (const float*)d_in[8];
    const float* Wout  = (const float*)d_in[9];
    const float* bout  = (const float*)d_in[10];
    float* out = (float*)d_out;

    int E = in_sizes[1] / 2;

    float *xl, *xr, *xres, *h;
    cudaGetSymbolAddress((void**)&xl,   g_xl);
    cudaGetSymbolAddress((void**)&xr,   g_xr);
    cudaGetSymbolAddress((void**)&xres, g_xres);
    cudaGetSymbolAddress((void**)&h,    g_h);

    cudaFuncSetAttribute(gemm_k, cudaFuncAttributeMaxDynamicSharedMemorySize, SM_SZ);

    const int ACONV_G = (NP * 32) / 256;   // 6256
    dim3 wg3(3, 16);
    dim3 wg1(1, 16);
    dim3 gg3(3, NP / 128);

    // layer-0 GEMM pipeline first (positions ~4-5 for ncu capture window)
    detect_dtype_k<<<1, 32>>>((const unsigned int*)ei);
    aconv_k<<<ACONV_G, 256>>>(x, NN, 0);
    wconv_k<<<wg3, 256>>>(Wl, Wr, Wres);
    gemm_k<<<dim3(3, 196), 256, SM_SZ>>>(xl, xr, xres, 0);
    gemm_k<<<dim3(3, 195), 256, SM_SZ>>>(xl, xr, xres, 196);

    // CSR build
    zero_cnt_k<<<(NN + 255) / 256, 256>>>();
    count_k<<<(E + 255) / 256, 256>>>(ei, E);
    int nb = (NN + 511) / 512;
    scan1_k<<<nb, 512>>>();
    scan2_k<<<1, 128>>>(nb);
    scan3_k<<<nb, 512>>>();
    fill_k<<<(E + 255) / 256, 256>>>(ei, E);

    for (int i = 0; i < LL; i++) {
        if (i > 0) {
            aconv_k<<<ACONV_G, 256>>>(h, NN, 1);
            wconv_k<<<wg3, 256>>>(Wl + (size_t)i * DD * DD, Wr + (size_t)i * DD * DD,
                                  Wres + (size_t)i * DD * DD);
            gemm_k<<<gg3, 256, SM_SZ>>>(xl, xr, xres, 0);
        }
        gat_warp_k<<<NN / 8, 256>>>(xl, xr, xres, bias + (size_t)i * DD,
                                    att + (size_t)i * HH * CC, h);
        bn_zero_k<<<1, DD>>>();
        bn_stats_k<<<400, DD>>>(h);
        bn_final_k<<<1, DD>>>(gamma + (size_t)i * DD, beta + (size_t)i * DD);
    }

    // final linear
    aconv_k<<<ACONV_G, 256>>>(h, NN, 1);
    wconv_k<<<wg1, 256>>>(Wout, nullptr, nullptr);
    gemm_k<<<dim3(1, NP / 128), 256, SM_SZ>>>(xl, nullptr, nullptr, 0);
    bias_copy_k<<<(NN * 32 + 255) / 256, 256>>>(xl, bout, out);
}